// round 4
// baseline (speedup 1.0000x reference)
#include <cuda_runtime.h>
#include <math.h>

#define E_    2048
#define S_    256
#define Q_    25
#define NN_   36
#define R_    15
#define H_    128
#define K2_   72           // 2*NN_
#define SR_   3840         // S_*R_
#define NPTS  (E_*NN_)     // 73728
#define PPB   64           // points per MLP block
#define MLP_BLOCKS (NPTS/PPB)   // 1152
#define STAGE1_BLOCKS (MLP_BLOCKS + S_)  // 1408
#define GX 30              // N tiles (3840/128)
#define GY 16              // M tiles (2048/128)
#define NPART (GX*GY)      // 480

#define ASTRIDE 68         // 64 + 4 pad
#define CSTRIDE 132        // 128 + 4 pad

// ---- scratch ----
__device__ float g_evcat[E_*K2_];
__device__ float g_Acat[SR_*K2_];
__device__ float g_partial[NPART];
__device__ unsigned g_count = 0;

// ---- packed f32x2 helpers ----
typedef unsigned long long u64t;
__device__ __forceinline__ u64t pk2(float lo, float hi){
    u64t r; asm("mov.b64 %0,{%1,%2};" : "=l"(r) : "f"(lo), "f"(hi)); return r;
}
__device__ __forceinline__ u64t fma2(u64t a, u64t b, u64t c){
    u64t d; asm("fma.rn.f32x2 %0,%1,%2,%3;" : "=l"(d) : "l"(a), "l"(b), "l"(c)); return d;
}
__device__ __forceinline__ void upk2(u64t x, float& lo, float& hi){
    asm("mov.b64 {%0,%1},%2;" : "=f"(lo), "=f"(hi) : "l"(x));
}
union F4U { float4 f; u64t u[2]; };

// fast tanh: 1 - 2/(exp(2x)+1)
__device__ __forceinline__ float fast_tanh(float x){
    float e;
    asm("ex2.approx.f32 %0, %1;" : "=f"(e) : "f"(x * 2.885390081777926f));
    float r;
    asm("rcp.approx.f32 %0, %1;" : "=f"(r) : "f"(e + 1.0f));
    return 1.0f - 2.0f * r;
}

// ============================================================
// MLP layer on 64 points, 128 threads, 4m x 16n per thread.
// Hout[j][p] = tanh(sum_k Hin[k][p]*W[k][j] + b[j])
// ============================================================
__device__ __forceinline__ void gemm_layer64(const float* __restrict__ Hin, float* __restrict__ Hout,
                                             const float* __restrict__ W, const float* __restrict__ b){
    const int tid = threadIdx.x;
    const int tx = tid & 7, ty = tid >> 3;     // tx: 8 (n0=tx*16), ty: 16 (m0=ty*4)
    const int m0 = ty * 4, n0 = tx * 16;

    u64t acc[4][8];
    #pragma unroll
    for (int np = 0; np < 8; np++){
        u64t bb = pk2(__ldg(&b[n0 + 2*np]), __ldg(&b[n0 + 2*np + 1]));
        #pragma unroll
        for (int m = 0; m < 4; m++) acc[m][np] = bb;
    }

    // prefetch k=0
    float4 a = *(const float4*)(Hin + m0);
    F4U w0, w1, w2, w3;
    w0.f = __ldg((const float4*)(W + n0));
    w1.f = __ldg((const float4*)(W + n0 + 4));
    w2.f = __ldg((const float4*)(W + n0 + 8));
    w3.f = __ldg((const float4*)(W + n0 + 12));

    #pragma unroll 2
    for (int k = 0; k < H_; k++){
        float4 an; F4U w0n, w1n, w2n, w3n;
        if (k < H_ - 1){
            an   = *(const float4*)(Hin + (k+1)*ASTRIDE + m0);
            w0n.f = __ldg((const float4*)(W + (k+1)*H_ + n0));
            w1n.f = __ldg((const float4*)(W + (k+1)*H_ + n0 + 4));
            w2n.f = __ldg((const float4*)(W + (k+1)*H_ + n0 + 8));
            w3n.f = __ldg((const float4*)(W + (k+1)*H_ + n0 + 12));
        }
        u64t bv[8] = { w0.u[0], w0.u[1], w1.u[0], w1.u[1],
                       w2.u[0], w2.u[1], w3.u[0], w3.u[1] };
        float av[4] = { a.x, a.y, a.z, a.w };
        #pragma unroll
        for (int m = 0; m < 4; m++){
            u64t ad = pk2(av[m], av[m]);
            #pragma unroll
            for (int np = 0; np < 8; np++) acc[m][np] = fma2(ad, bv[np], acc[m][np]);
        }
        a = an; w0 = w0n; w1 = w1n; w2 = w2n; w3 = w3n;
    }

    #pragma unroll
    for (int m = 0; m < 4; m++){
        #pragma unroll
        for (int np = 0; np < 8; np++){
            float lo, hi; upk2(acc[m][np], lo, hi);
            Hout[(n0 + 2*np    )*ASTRIDE + m0 + m] = fast_tanh(lo);
            Hout[(n0 + 2*np + 1)*ASTRIDE + m0 + m] = fast_tanh(hi);
        }
    }
}

// ============================================================
// Stage 1: blocks [0,1152) MLP; blocks [1152,1408) build Acat.
// ============================================================
__global__ __launch_bounds__(128, 3)
void stage1(const float* __restrict__ nodes,
            const float* __restrict__ W1, const float* __restrict__ b1,
            const float* __restrict__ W2, const float* __restrict__ b2,
            const float* __restrict__ W3, const float* __restrict__ b3,
            const float* __restrict__ W4, const float* __restrict__ b4,
            const float* __restrict__ BDD,
            const float* __restrict__ Ixx, const float* __restrict__ Iyy,
            const float* __restrict__ wq,  const float* __restrict__ Base){
    extern __shared__ float sm[];
    const int tid = threadIdx.x;

    if (blockIdx.x >= MLP_BLOCKS){
        const int s = blockIdx.x - MLP_BLOCKS;
        float* WB  = sm;
        float* sI0 = WB  + Q_*R_;
        float* sI1 = sI0 + Q_*NN_;

        for (int i = tid; i < Q_*R_; i += 128){
            int q = i / R_, r = i - q*R_;
            WB[i] = wq[q] * Base[q*R_ + r];
        }
        for (int i = tid; i < Q_*NN_; i += 128){
            sI0[i] = Ixx[s*Q_*NN_ + i];
            sI1[i] = Iyy[s*Q_*NN_ + i];
        }
        __syncthreads();

        for (int idx = tid; idx < R_*K2_; idx += 128){
            int r = idx / K2_, n = idx - r*K2_;
            const float* I = (n < NN_) ? sI0 : sI1;
            int nn = (n < NN_) ? n : (n - NN_);
            float acc = 0.f;
            #pragma unroll
            for (int q = 0; q < Q_; q++) acc += WB[q*R_ + r] * I[q*NN_ + nn];
            g_Acat[(s*R_ + r)*K2_ + n] = acc;
        }
        return;
    }

    float* Ha = sm;                       // [128][ASTRIDE]
    float* Hb = sm + H_*ASTRIDE;
    __shared__ float xs[PPB][2];

    const int p0 = blockIdx.x * PPB;
    ((float*)xs)[tid] = nodes[p0*2 + tid];
    __syncthreads();

    for (int idx = tid; idx < H_*PPB; idx += 128){
        int j = idx >> 6, p = idx & 63;
        float pre = xs[p][0]*__ldg(&W1[j]) + xs[p][1]*__ldg(&W1[H_ + j]) + __ldg(&b1[j]);
        Ha[j*ASTRIDE + p] = fast_tanh(pre);
    }
    __syncthreads();

    gemm_layer64(Ha, Hb, W2, b2);  __syncthreads();
    gemm_layer64(Hb, Ha, W3, b3);  __syncthreads();

    if (tid < PPB){
        float acc = 0.f;
        #pragma unroll 8
        for (int k = 0; k < H_; k++) acc += Ha[k*ASTRIDE + tid] * __ldg(&W4[k]);
        float ev = acc + __ldg(&b4[0]);
        int p = p0 + tid;
        int e = p / NN_, n = p - e*NN_;
        float c00 = __ldg(&BDD[e*4 + 0]), c01 = __ldg(&BDD[e*4 + 1]);
        float c10 = __ldg(&BDD[e*4 + 2]), c11 = __ldg(&BDD[e*4 + 3]);
        g_evcat[e*K2_ + n]       = (c00 + c10) * ev;
        g_evcat[e*K2_ + NN_ + n] = (c01 + c11) * ev;
    }
}

// ============================================================
// Stage 2: 128x128 tiles, 128 threads, 8m x 16n per thread.
// u = -J*(evcat @ Acat^T); fused loss; last-block final reduce.
// ============================================================
__global__ __launch_bounds__(128, 2)
void gemm_loss(const float* __restrict__ J, const float* __restrict__ F,
               float* __restrict__ out){
    extern __shared__ float sm[];
    float* As = sm;                    // [72][CSTRIDE]  (k-major, m fastest)
    float* Bs = sm + K2_*CSTRIDE;      // [72][CSTRIDE]  (k-major, n fastest)
    const int tid = threadIdx.x;
    const int m0g = blockIdx.y * 128, n0g = blockIdx.x * 128;

    for (int idx = tid; idx < 128*K2_; idx += 128){
        int m = idx / K2_, k = idx - m*K2_;
        As[k*CSTRIDE + m] = g_evcat[(m0g + m)*K2_ + k];
    }
    for (int idx = tid; idx < 128*K2_; idx += 128){
        int n = idx / K2_, k = idx - n*K2_;
        Bs[k*CSTRIDE + n] = g_Acat[(n0g + n)*K2_ + k];
    }
    __syncthreads();

    const int tx = tid & 7, ty = tid >> 3;   // n0 = tx*16, m0 = ty*8
    const int m0 = ty * 8, n0 = tx * 16;

    u64t acc[8][8];
    #pragma unroll
    for (int i = 0; i < 8; i++)
        #pragma unroll
        for (int np = 0; np < 8; np++) acc[i][np] = 0ULL;

    // prefetch k=0
    float4 a0 = *(const float4*)(As + m0);
    float4 a1 = *(const float4*)(As + m0 + 4);
    F4U b0, b1, b2, b3;
    b0.f = *(const float4*)(Bs + n0);
    b1.f = *(const float4*)(Bs + n0 + 4);
    b2.f = *(const float4*)(Bs + n0 + 8);
    b3.f = *(const float4*)(Bs + n0 + 12);

    #pragma unroll 2
    for (int k = 0; k < K2_; k++){
        float4 a0n, a1n; F4U b0n, b1n, b2n, b3n;
        if (k < K2_ - 1){
            const float* Ak = As + (k+1)*CSTRIDE;
            const float* Bk = Bs + (k+1)*CSTRIDE;
            a0n = *(const float4*)(Ak + m0);
            a1n = *(const float4*)(Ak + m0 + 4);
            b0n.f = *(const float4*)(Bk + n0);
            b1n.f = *(const float4*)(Bk + n0 + 4);
            b2n.f = *(const float4*)(Bk + n0 + 8);
            b3n.f = *(const float4*)(Bk + n0 + 12);
        }
        u64t bv[8] = { b0.u[0], b0.u[1], b1.u[0], b1.u[1],
                       b2.u[0], b2.u[1], b3.u[0], b3.u[1] };
        float av[8] = { a0.x, a0.y, a0.z, a0.w, a1.x, a1.y, a1.z, a1.w };
        #pragma unroll
        for (int i = 0; i < 8; i++){
            u64t ad = pk2(av[i], av[i]);
            #pragma unroll
            for (int np = 0; np < 8; np++) acc[i][np] = fma2(ad, bv[np], acc[i][np]);
        }
        a0 = a0n; a1 = a1n; b0 = b0n; b1 = b1n; b2 = b2n; b3 = b3n;
    }

    // fused epilogue: res = -J*dot - F; accumulate res^2 (vectorized F loads)
    float lsum = 0.f;
    #pragma unroll
    for (int i = 0; i < 8; i++){
        int e = m0g + m0 + i;
        const float* Fr = F + e*SR_ + n0g + n0;
        const float* Jr = J + e*S_;
        float4 f0 = __ldg((const float4*)(Fr));
        float4 f1 = __ldg((const float4*)(Fr + 4));
        float4 f2 = __ldg((const float4*)(Fr + 8));
        float4 f3 = __ldg((const float4*)(Fr + 12));
        float fv[16] = { f0.x,f0.y,f0.z,f0.w, f1.x,f1.y,f1.z,f1.w,
                         f2.x,f2.y,f2.z,f2.w, f3.x,f3.y,f3.z,f3.w };
        #pragma unroll
        for (int np = 0; np < 8; np++){
            float lo, hi; upk2(acc[i][np], lo, hi);
            int n  = n0g + n0 + 2*np;
            float j0 = __ldg(&Jr[(n    ) / R_]);
            float j1 = __ldg(&Jr[(n + 1) / R_]);
            float r0 = -j0*lo - fv[2*np];
            float r1 = -j1*hi - fv[2*np + 1];
            lsum += r0*r0 + r1*r1;
        }
    }

    __shared__ float red[128];
    red[tid] = lsum; __syncthreads();
    #pragma unroll
    for (int s = 64; s > 0; s >>= 1){
        if (tid < s) red[tid] += red[tid + s];
        __syncthreads();
    }

    __shared__ unsigned s_last;
    if (tid == 0){
        g_partial[blockIdx.y * GX + blockIdx.x] = red[0];
        __threadfence();
        unsigned t = atomicAdd(&g_count, 1u);
        s_last = (t == NPART - 1u) ? 1u : 0u;
    }
    __syncthreads();

    if (s_last){
        __shared__ double dred[128];
        double s = 0.0;
        for (int i = tid; i < NPART; i += 128) s += (double)g_partial[i];
        dred[tid] = s; __syncthreads();
        #pragma unroll
        for (int k = 64; k > 0; k >>= 1){
            if (tid < k) dred[tid] += dred[tid + k];
            __syncthreads();
        }
        if (tid == 0){
            out[0] = (float)(dred[0] / (double)R_);
            g_count = 0;
        }
    }
}

// ============================================================
extern "C" void kernel_launch(void* const* d_in, const int* in_sizes, int n_in,
                              void* d_out, int out_size){
    const float* nodes = (const float*)d_in[0];
    const float* W1    = (const float*)d_in[1];
    const float* b1    = (const float*)d_in[2];
    const float* W2    = (const float*)d_in[3];
    const float* b2    = (const float*)d_in[4];
    const float* W3    = (const float*)d_in[5];
    const float* b3    = (const float*)d_in[6];
    const float* W4    = (const float*)d_in[7];
    const float* b4    = (const float*)d_in[8];
    const float* Ixx   = (const float*)d_in[9];
    const float* Iyy   = (const float*)d_in[10];
    const float* BDD   = (const float*)d_in[11];
    const float* wq    = (const float*)d_in[12];
    const float* Base  = (const float*)d_in[13];
    const float* J     = (const float*)d_in[14];
    const float* F     = (const float*)d_in[15];

    const int s1_smem   = 2 * H_ * ASTRIDE * 4;       // 69632 B
    const int gemm_smem = 2 * K2_ * CSTRIDE * 4;      // 76032 B
    cudaFuncSetAttribute(stage1,    cudaFuncAttributeMaxDynamicSharedMemorySize, s1_smem);
    cudaFuncSetAttribute(gemm_loss, cudaFuncAttributeMaxDynamicSharedMemorySize, gemm_smem);

    stage1<<<STAGE1_BLOCKS, 128, s1_smem>>>(nodes, W1, b1, W2, b2, W3, b3, W4, b4,
                                            BDD, Ixx, Iyy, wq, Base);
    gemm_loss<<<dim3(GX, GY), 128, gemm_smem>>>(J, F, (float*)d_out);
}